// round 2
// baseline (speedup 1.0000x reference)
#include <cuda_runtime.h>

typedef unsigned long long ULL;

// ---------------- device scratch (no allocations allowed) ----------------
// Packed, zero-padded weights: Wpad[lp][c] = (Win_real[c][lp-9], Win_imag[c][lp-9]),
// zero outside l in [0, 4086]. lp in [0, 4105).
__device__ float2 wpad_g[4105 * 16];
// Stage-1 partial sums: [b][s][c][w][2]  (b:256, s:8, c:16, w:10)
__device__ float fpart_g[256 * 8 * 320];
// Pre-batchnorm output: [b][c*2+o]
__device__ float out_g[256 * 32];

// ---------------- packed f32x2 FMA (FFMA2) ----------------
__device__ __forceinline__ ULL fma2(ULL a, ULL b, ULL c) {
    ULL d;
    asm("fma.rn.f32x2 %0, %1, %2, %3;" : "=l"(d) : "l"(a), "l"(b), "l"(c));
    return d;
}

// ---------------- kernel 0: pack + pad weights ----------------
__global__ void pack_kernel(const float* __restrict__ wr, const float* __restrict__ wi) {
    int idx = blockIdx.x * blockDim.x + threadIdx.x;
    if (idx >= 4105 * 16) return;
    int lp = idx >> 4;
    int c  = idx & 15;
    int l  = lp - 9;
    float2 v = make_float2(0.f, 0.f);
    if (l >= 0 && l < 4087) {
        v.x = wr[c * 4087 + l];
        v.y = wi[c * 4087 + l];
    }
    wpad_g[lp * 16 + c] = v;
}

// ---------------- kernel 1: depthwise sliding filters (stage 1) ----------------
// grid (256, 8), block 256 = 16 channels x 16 n-chunks; each thread does 32
// contiguous positions with a rotating 10-deep register weight window.
__global__ void __launch_bounds__(256) stage1_kernel(const float* __restrict__ x) {
    __shared__ float red[16][322];   // [j][(c*10+w)*2+comp], padded row

    int b = blockIdx.x;
    int s = blockIdx.y;
    int tid = threadIdx.x;
    int c = tid & 15;
    int j = tid >> 4;
    int ps = s * 512 + j * 32;       // starting position p for this thread

    const ULL* xp = (const ULL*)x + ((size_t)b * 4096 + (size_t)ps) * 16 + c;
    const ULL* wp = (const ULL*)wpad_g + (size_t)ps * 16 + c;

    // slot m holds Wt[l] with l == m-9 (mod 10); init window Wt[ps .. ps+8]
    ULL wbuf[10];
#pragma unroll
    for (int k = 0; k < 9; k++) wbuf[k] = wp[(size_t)k * 16];

    ULL acc[10];
#pragma unroll
    for (int w = 0; w < 10; w++) acc[w] = 0ULL;

#pragma unroll
    for (int t = 0; t < 32; t++) {
        ULL xv = xp[(size_t)t * 16];
        wbuf[(t + 9) % 10] = wp[(size_t)(t + 9) * 16];   // Wpad[ps+t+9]
#pragma unroll
        for (int w = 0; w < 10; w++)
            acc[w] = fma2(xv, wbuf[(t + 9 - w) % 10], acc[w]);  // Wpad[p-w+9]
    }

    // dump to smem: red[j][(c*10+w)*2 + comp]
#pragma unroll
    for (int w = 0; w < 10; w++) {
        red[j][(c * 10 + w) * 2 + 0] = __uint_as_float((unsigned)(acc[w] & 0xffffffffULL));
        red[j][(c * 10 + w) * 2 + 1] = __uint_as_float((unsigned)(acc[w] >> 32));
    }
    __syncthreads();

    // reduce the 16 n-chunks over all 320 entries with 256 threads
    for (int idx = tid; idx < 320; idx += 256) {
        float v = 0.f;
#pragma unroll
        for (int jj = 0; jj < 16; jj++) v += red[jj][idx];
        fpart_g[((size_t)(b * 8 + s)) * 320 + idx] = v;
    }
}

// ---------------- kernel 2: amp nonlinearity + Linear(2C->2) + out filter ----------------
// one block per b, 320 threads
__global__ void __launch_bounds__(320) stage23_kernel(const float* __restrict__ Wnl,
                                                      const float* __restrict__ WoR,
                                                      const float* __restrict__ WoI) {
    __shared__ float tf[10][32];       // [w][i], i<16: amp*fr, i>=16: amp*fi
    __shared__ float contrib[10][32];  // [w][c*2+o]

    int b = blockIdx.x;
    int tid = threadIdx.x;

    if (tid < 160) {
        int w = tid / 16;
        int c = tid & 15;
        float fr = 0.f, fi = 0.f;
#pragma unroll
        for (int s = 0; s < 8; s++) {
            const float* fp = fpart_g + ((size_t)(b * 8 + s)) * 320 + (c * 10 + w) * 2;
            fr += fp[0];
            fi += fp[1];
        }
        float amp = fr * fr + fi * fi;
        tf[w][c]      = amp * fr;
        tf[w][16 + c] = amp * fi;
    }
    __syncthreads();

    {
        int w = tid >> 5;
        int q = tid & 31;
        int c = q >> 1;
        int o = q & 1;
        float acc = 0.f;
        const float* wn = Wnl + (c * 2 + o) * 32;
#pragma unroll
        for (int i = 0; i < 32; i++) acc += tf[w][i] * wn[i];
        float wo = (o == 0 ? WoR : WoI)[c * 10 + w];
        contrib[w][q] = acc * wo;
    }
    __syncthreads();

    if (tid < 32) {
        float ssum = 0.f;
#pragma unroll
        for (int ww = 0; ww < 10; ww++) ssum += contrib[ww][tid];
        out_g[b * 32 + tid] = ssum;
    }
}

// ---------------- kernel 3: BatchNorm1d (training-mode stats) ----------------
// one block per channel, 512 threads = 256 b x 2 comps; two-pass mean/var
__global__ void __launch_bounds__(512) bn_kernel(const float* __restrict__ gamma,
                                                 const float* __restrict__ beta,
                                                 float* __restrict__ out) {
    __shared__ float sbuf[16];
    __shared__ float stat;

    int c = blockIdx.x;
    int t = threadIdx.x;
    int b = t >> 1;
    int o = t & 1;

    float v = out_g[b * 32 + c * 2 + o];

    // pass 1: mean
    float r = v;
#pragma unroll
    for (int off = 16; off; off >>= 1) r += __shfl_xor_sync(0xffffffffu, r, off);
    if ((t & 31) == 0) sbuf[t >> 5] = r;
    __syncthreads();
    if (t < 32) {
        float z = (t < 16) ? sbuf[t] : 0.f;
#pragma unroll
        for (int off = 8; off; off >>= 1) z += __shfl_xor_sync(0xffffffffu, z, off);
        if (t == 0) stat = z * (1.f / 512.f);
    }
    __syncthreads();
    float mean = stat;
    float d = v - mean;

    // pass 2: variance of centered values
    r = d * d;
#pragma unroll
    for (int off = 16; off; off >>= 1) r += __shfl_xor_sync(0xffffffffu, r, off);
    if ((t & 31) == 0) sbuf[t >> 5] = r;
    __syncthreads();
    if (t < 32) {
        float z = (t < 16) ? sbuf[t] : 0.f;
#pragma unroll
        for (int off = 8; off; off >>= 1) z += __shfl_xor_sync(0xffffffffu, z, off);
        if (t == 0) stat = rsqrtf(z * (1.f / 512.f) + 1e-5f);
    }
    __syncthreads();

    out[b * 32 + c * 2 + o] = d * stat * gamma[c] + beta[c];
}

// ---------------- launch ----------------
extern "C" void kernel_launch(void* const* d_in, const int* in_sizes, int n_in,
                              void* d_out, int out_size) {
    const float* x     = (const float*)d_in[0];
    const float* wir   = (const float*)d_in[1];
    const float* wii   = (const float*)d_in[2];
    const float* wnl   = (const float*)d_in[3];
    const float* wor   = (const float*)d_in[4];
    const float* woi   = (const float*)d_in[5];
    const float* gamma = (const float*)d_in[6];
    const float* beta  = (const float*)d_in[7];
    float* out = (float*)d_out;

    pack_kernel<<<(4105 * 16 + 255) / 256, 256>>>(wir, wii);
    stage1_kernel<<<dim3(256, 8), 256>>>(x);
    stage23_kernel<<<256, 320>>>(wnl, wor, woi);
    bn_kernel<<<16, 512>>>(gamma, beta, out);
}